// round 8
// baseline (speedup 1.0000x reference)
#include <cuda_runtime.h>
#include <math.h>

#define BB    16
#define MMM   1024
#define NN    512
#define CC    8
#define COUT  64
#define NSLC  4               // n-slices (CTAs) per (b, mtile) group
#define NSL   (NN / NSLC)     // 128 n per slice
#define NWARP 8
#define NPW   (NSL / NWARP)   // 16 n per warp
#define MPB   64              // m per group (2 per lane)
#define TPB   (32 * NWARP)    // 256 threads
#define NGRP  (BB * (MMM / MPB))  // 256 groups

__device__ float g_part[NGRP * NSLC * CC * MPB];  // 2MB partials
__device__ int   g_cnt[NGRP];                      // zero-init; self-resetting

__device__ __forceinline__ float ex2f(float x) {
    float y;
    asm("ex2.approx.ftz.f32 %0, %1;" : "=f"(y) : "f"(x));
    return y;
}
__device__ __forceinline__ unsigned long long pack2(float lo, float hi) {
    unsigned long long r;
    asm("mov.b64 %0, {%1, %2};" : "=l"(r) : "f"(lo), "f"(hi));
    return r;
}
__device__ __forceinline__ void unpack2(unsigned long long v, float& lo, float& hi) {
    asm("mov.b64 {%0, %1}, %2;" : "=f"(lo), "=f"(hi) : "l"(v));
}
__device__ __forceinline__ void ffma2(unsigned long long& d, unsigned long long a, unsigned long long b) {
    asm("fma.rn.f32x2 %0, %1, %2, %0;" : "+l"(d) : "l"(a), "l"(b));
}

__global__ __launch_bounds__(TPB)
void convdeepset_kernel(const float* __restrict__ ci,    // (B,N,1)
                        const float* __restrict__ co,    // (B,N,7)
                        const float* __restrict__ ti,    // (B,M,1)
                        const float* __restrict__ sigma, // (8,)
                        const float* __restrict__ W,     // (64,8)
                        const float* __restrict__ bias,  // (64,)
                        float* __restrict__ out)         // (B,M,64)
{
    __shared__ float4      s_ab2[NSL / 2];           // (a0,b0,a1,b1) per local n-pair
    __shared__ ulonglong2  s_cx[NSL * 2];            // packed f32x2 channels
    __shared__ float       s_part[NWARP][CC][MPB];   // 16KB
    __shared__ float       s_v[CC][MPB];
    __shared__ float       s_dens[MPB];
    __shared__ float       s_Wt[CC][COUT];
    __shared__ float       s_bias[COUT];
    __shared__ int         s_win;

    const int tid  = threadIdx.x;
    const int w    = tid >> 5;
    const int lane = tid & 31;
    const int blk  = blockIdx.x;
    const int ns   = blk & (NSLC - 1);
    const int grp  = blk >> 2;          // 0..255
    const int mt   = grp & 15;
    const int b    = grp >> 4;
    const int mbase  = mt * MPB;
    const int nsbase = ns * NSL;

    // uniform-sigma detection
    const float LOG2E = 1.4426950408889634f;
    float sg0 = sigma[0];
    bool uni = true;
    #pragma unroll
    for (int c = 1; c < CC; c++) uni &= (sigma[c] == sg0);
    const float k2u = -0.5f * LOG2E * expf(-2.0f * sg0);

    // stage this slice's context rows
    const float* cib = ci + (size_t)b * NN + nsbase;
    const float* cob = co + ((size_t)b * NN + nsbase) * 7;
    float2* s_abf2 = (float2*)s_ab2;
    if (tid < NSL) {
        int i = tid;
        float x = cib[i];
        float2 ab;
        if (uni) { ab.x = k2u * x * x; ab.y = -2.0f * k2u * x; }
        else     { ab.x = x;           ab.y = 0.0f; }
        s_abf2[i] = ab;
        const float* r = cob + i * 7;
        s_cx[2 * i]     = make_ulonglong2(pack2(1.0f, r[0]), pack2(r[1], r[2]));
        s_cx[2 * i + 1] = make_ulonglong2(pack2(r[3], r[4]), pack2(r[5], r[6]));
    }
    __syncthreads();

    const float t0 = ti[(size_t)b * MMM + mbase + lane];
    const float t1 = ti[(size_t)b * MMM + mbase + lane + 32];

    const int l0 = w * NPW;
    float f0[CC], f1[CC];

    if (uni) {
        unsigned long long x0 = 0ull, x1 = 0ull, x2 = 0ull, x3 = 0ull;
        unsigned long long y0 = 0ull, y1 = 0ull, y2 = 0ull, y3 = 0ull;
        #pragma unroll
        for (int i = 0; i < NPW / 2; i++) {
            const int np = (l0 >> 1) + i;
            const int n  = l0 + 2 * i;
            float4 ab = s_ab2[np];
            float wa0 = ex2f(fmaf(ab.y, t0, ab.x));
            float wb0 = ex2f(fmaf(ab.w, t0, ab.z));
            float wa1 = ex2f(fmaf(ab.y, t1, ab.x));
            float wb1 = ex2f(fmaf(ab.w, t1, ab.z));
            ulonglong2 pa = s_cx[2 * n];
            ulonglong2 qa = s_cx[2 * n + 1];
            ulonglong2 pb = s_cx[2 * n + 2];
            ulonglong2 qb = s_cx[2 * n + 3];
            unsigned long long wa0p = pack2(wa0, wa0);
            unsigned long long wb0p = pack2(wb0, wb0);
            unsigned long long wa1p = pack2(wa1, wa1);
            unsigned long long wb1p = pack2(wb1, wb1);
            ffma2(x0, wa0p, pa.x); ffma2(x1, wa0p, pa.y);
            ffma2(x2, wa0p, qa.x); ffma2(x3, wa0p, qa.y);
            ffma2(x0, wb0p, pb.x); ffma2(x1, wb0p, pb.y);
            ffma2(x2, wb0p, qb.x); ffma2(x3, wb0p, qb.y);
            ffma2(y0, wa1p, pa.x); ffma2(y1, wa1p, pa.y);
            ffma2(y2, wa1p, qa.x); ffma2(y3, wa1p, qa.y);
            ffma2(y0, wb1p, pb.x); ffma2(y1, wb1p, pb.y);
            ffma2(y2, wb1p, qb.x); ffma2(y3, wb1p, qb.y);
        }
        unpack2(x0, f0[0], f0[1]); unpack2(x1, f0[2], f0[3]);
        unpack2(x2, f0[4], f0[5]); unpack2(x3, f0[6], f0[7]);
        unpack2(y0, f1[0], f1[1]); unpack2(y1, f1[2], f1[3]);
        unpack2(y2, f1[4], f1[5]); unpack2(y3, f1[6], f1[7]);
    } else {
        float k2[CC];
        #pragma unroll
        for (int c = 0; c < CC; c++) k2[c] = -0.5f * LOG2E * expf(-2.0f * sigma[c]);
        #pragma unroll
        for (int c = 0; c < CC; c++) { f0[c] = 0.0f; f1[c] = 0.0f; }
        for (int i = 0; i < NPW; i++) {
            int n = l0 + i;
            float x = s_abf2[n].x;
            float d0 = (x - t0) * (x - t0);
            float d1 = (x - t1) * (x - t1);
            const float* cf = (const float*)&s_cx[2 * n];
            #pragma unroll
            for (int c = 0; c < CC; c++) {
                f0[c] += ex2f(d0 * k2[c]) * cf[c];
                f1[c] += ex2f(d1 * k2[c]) * cf[c];
            }
        }
    }

    #pragma unroll
    for (int c = 0; c < CC; c++) {
        s_part[w][c][lane]      = f0[c];
        s_part[w][c][lane + 32] = f1[c];
    }
    __syncthreads();

    // in-CTA reduce over 8 warps -> write 512-float partial for this slice
    {
        const int c   = tid >> 5;
        const int mm0 = tid & 31;
        float acc0 = 0.0f, acc1 = 0.0f;
        #pragma unroll
        for (int ww = 0; ww < NWARP; ww++) {
            acc0 += s_part[ww][c][mm0];
            acc1 += s_part[ww][c][mm0 + 32];
        }
        float* pp = g_part + ((size_t)grp * NSLC + ns) * (CC * MPB) + c * MPB;
        pp[mm0]      = acc0;
        pp[mm0 + 32] = acc1;
    }

    // signal completion; last CTA of the group runs the epilogue
    __threadfence();
    __syncthreads();
    if (tid == 0) {
        int old = atomicAdd(&g_cnt[grp], 1);
        s_win = (old == NSLC - 1);
    }
    __syncthreads();
    if (!s_win) return;
    __threadfence();

    // ---- winner: sum 4 slices, normalize, GEMM ----
    for (int i = tid; i < CC * COUT; i += TPB) {      // FIXED: was `if (tid < CC*COUT)` with TPB=256 < 512
        int o = i / CC, c = i % CC;
        s_Wt[c][o] = W[i];
    }
    if (tid < COUT) s_bias[tid] = bias[tid];

    {
        const int c   = tid >> 5;
        const int mm0 = tid & 31;
        const float* base = g_part + (size_t)grp * NSLC * (CC * MPB) + c * MPB;
        float acc0 = 0.0f, acc1 = 0.0f;
        #pragma unroll
        for (int s = 0; s < NSLC; s++) {
            acc0 += base[s * (CC * MPB) + mm0];
            acc1 += base[s * (CC * MPB) + mm0 + 32];
        }
        if (c == 0) { s_dens[mm0] = acc0; s_dens[mm0 + 32] = acc1; }
        __syncthreads();

        float ta = ti[(size_t)b * MMM + mbase + mm0];
        float tb = ti[(size_t)b * MMM + mbase + mm0 + 32];
        float ga = uni ? ex2f(k2u * ta * ta) : 1.0f;
        float gb = uni ? ex2f(k2u * tb * tb) : 1.0f;
        float da = s_dens[mm0] * ga;             // true density
        float db = s_dens[mm0 + 32] * gb;
        float inva = ga / (da + 1e-8f);
        float invb = gb / (db + 1e-8f);
        s_v[c][mm0]      = (c == 0) ? da : acc0 * inva;
        s_v[c][mm0 + 32] = (c == 0) ? db : acc1 * invb;
        __syncthreads();
    }

    // (8 -> 64) GEMM + bias; thread = (mm = tid>>2, og = tid&3), 16 outputs
    {
        const int mm = tid >> 2;
        const int og = tid & 3;
        float v[CC];
        #pragma unroll
        for (int c = 0; c < CC; c++) v[c] = s_v[c][mm];

        float4* outp = (float4*)(out + ((size_t)(b * MMM + mbase + mm)) * COUT + og * 16);
        #pragma unroll
        for (int j = 0; j < 4; j++) {
            int o4 = og * 4 + j;
            float4 r = *(const float4*)&s_bias[o4 * 4];
            #pragma unroll
            for (int c = 0; c < CC; c++) {
                float4 w4 = *(const float4*)&s_Wt[c][o4 * 4];
                r.x = fmaf(v[c], w4.x, r.x);
                r.y = fmaf(v[c], w4.y, r.y);
                r.z = fmaf(v[c], w4.z, r.z);
                r.w = fmaf(v[c], w4.w, r.w);
            }
            outp[j] = r;
        }
    }

    // reset counter for next launch / graph replay
    if (tid == 0) g_cnt[grp] = 0;
}

extern "C" void kernel_launch(void* const* d_in, const int* in_sizes, int n_in,
                              void* d_out, int out_size) {
    const float* ci    = (const float*)d_in[0];
    const float* co    = (const float*)d_in[1];
    const float* ti    = (const float*)d_in[2];
    const float* sigma = (const float*)d_in[3];
    const float* W     = (const float*)d_in[4];
    const float* bias  = (const float*)d_in[5];
    float* out = (float*)d_out;

    convdeepset_kernel<<<NGRP * NSLC, TPB>>>(ci, co, ti, sigma, W, bias, out);  // 1024 CTAs
}

// round 9
// speedup vs baseline: 1.2592x; 1.2592x over previous
#include <cuda_runtime.h>
#include <math.h>

#define BB    16
#define MMM   1024
#define NN    512
#define CC    8
#define COUT  64
#define NWARP 8               // warps per CTA, each owns a 64-n slice
#define NPW   (NN / NWARP)    // 64 n per warp
#define MPB   32              // m per CTA (1 per lane)
#define TPB   (32 * NWARP)    // 256 threads

__device__ __forceinline__ float ex2f(float x) {
    float y;
    asm("ex2.approx.ftz.f32 %0, %1;" : "=f"(y) : "f"(x));
    return y;
}
__device__ __forceinline__ unsigned long long pack2(float lo, float hi) {
    unsigned long long r;
    asm("mov.b64 %0, {%1, %2};" : "=l"(r) : "f"(lo), "f"(hi));
    return r;
}
__device__ __forceinline__ void unpack2(unsigned long long v, float& lo, float& hi) {
    asm("mov.b64 {%0, %1}, %2;" : "=f"(lo), "=f"(hi) : "l"(v));
}
__device__ __forceinline__ void ffma2(unsigned long long& d, unsigned long long a, unsigned long long b) {
    asm("fma.rn.f32x2 %0, %1, %2, %0;" : "+l"(d) : "l"(a), "l"(b));
}

__global__ __launch_bounds__(TPB)
void convdeepset_kernel(const float* __restrict__ ci,    // (B,N,1)
                        const float* __restrict__ co,    // (B,N,7)
                        const float* __restrict__ ti,    // (B,M,1)
                        const float* __restrict__ sigma, // (8,)
                        const float* __restrict__ W,     // (64,8)
                        const float* __restrict__ bias,  // (64,)
                        float* __restrict__ out)         // (B,M,64)
{
    __shared__ float4      s_ab2[NN / 2];            // (a_n,b_n,a_{n+1},b_{n+1}) per n-pair (4KB)
    __shared__ ulonglong2  s_cx[NN * 2];             // packed f32x2 channels (16KB)
    __shared__ float       s_part[NWARP][CC][MPB];   // 8KB
    __shared__ float       s_v[CC][MPB];
    __shared__ float       s_dens[MPB];
    __shared__ float       s_Wt[CC][COUT];
    __shared__ float       s_bias[COUT];

    const int tid  = threadIdx.x;
    const int w    = tid >> 5;
    const int lane = tid & 31;
    const int blk  = blockIdx.x;
    const int b    = blk >> 5;          // 32 m-tiles per batch
    const int mt   = blk & 31;
    const int mbase = mt * MPB;

    // stage W^T + bias (strided: TPB=256 < 512 entries)
    for (int i = tid; i < CC * COUT; i += TPB) {
        int o = i / CC, c = i % CC;
        s_Wt[c][o] = W[i];
    }
    if (tid < COUT) s_bias[tid] = bias[tid];

    // uniform-sigma detection
    const float LOG2E = 1.4426950408889634f;
    float sg0 = sigma[0];
    bool uni = true;
    #pragma unroll
    for (int c = 1; c < CC; c++) uni &= (sigma[c] == sg0);
    const float k2u = -0.5f * LOG2E * expf(-2.0f * sg0);

    // stage context rows (2 per thread)
    const float* cib = ci + (size_t)b * NN;
    const float* cob = co + (size_t)b * NN * 7;
    float2* s_abf2 = (float2*)s_ab2;
    for (int i = tid; i < NN; i += TPB) {
        float x = cib[i];
        float2 ab;
        if (uni) { ab.x = k2u * x * x; ab.y = -2.0f * k2u * x; }
        else     { ab.x = x;           ab.y = 0.0f; }
        s_abf2[i] = ab;
        const float* r = cob + i * 7;
        s_cx[2 * i]     = make_ulonglong2(pack2(1.0f, r[0]), pack2(r[1], r[2]));
        s_cx[2 * i + 1] = make_ulonglong2(pack2(r[3], r[4]), pack2(r[5], r[6]));
    }
    __syncthreads();

    const float t = ti[(size_t)b * MMM + mbase + lane];

    const int n0 = w * NPW;
    float f[CC];

    if (uni) {
        // w' = exp2(a_n + b_n*t); exp2(k2 t^2) factor reapplied to density only
        unsigned long long a0 = 0ull, a1 = 0ull, a2 = 0ull, a3 = 0ull;
        #pragma unroll 4
        for (int i = 0; i < NPW / 2; i++) {
            const int np = (n0 >> 1) + i;
            const int n  = n0 + 2 * i;
            float4 ab = s_ab2[np];
            float wa = ex2f(fmaf(ab.y, t, ab.x));
            float wb = ex2f(fmaf(ab.w, t, ab.z));
            ulonglong2 pa = s_cx[2 * n];
            ulonglong2 qa = s_cx[2 * n + 1];
            ulonglong2 pb = s_cx[2 * n + 2];
            ulonglong2 qb = s_cx[2 * n + 3];
            unsigned long long wap = pack2(wa, wa);
            unsigned long long wbp = pack2(wb, wb);
            ffma2(a0, wap, pa.x); ffma2(a1, wap, pa.y);
            ffma2(a2, wap, qa.x); ffma2(a3, wap, qa.y);
            ffma2(a0, wbp, pb.x); ffma2(a1, wbp, pb.y);
            ffma2(a2, wbp, qb.x); ffma2(a3, wbp, qb.y);
        }
        unpack2(a0, f[0], f[1]); unpack2(a1, f[2], f[3]);
        unpack2(a2, f[4], f[5]); unpack2(a3, f[6], f[7]);
    } else {
        float k2[CC];
        #pragma unroll
        for (int c = 0; c < CC; c++) k2[c] = -0.5f * LOG2E * expf(-2.0f * sigma[c]);
        #pragma unroll
        for (int c = 0; c < CC; c++) f[c] = 0.0f;
        for (int i = 0; i < NPW; i++) {
            int n = n0 + i;
            float x = s_abf2[n].x;
            float diff = x - t;
            float d = diff * diff;
            const float* cf = (const float*)&s_cx[2 * n];
            #pragma unroll
            for (int c = 0; c < CC; c++) f[c] += ex2f(d * k2[c]) * cf[c];
        }
    }

    #pragma unroll
    for (int c = 0; c < CC; c++) s_part[w][c][lane] = f[c];
    __syncthreads();

    // stage 2: reduce 8 warps; thread = (c = tid>>5, mm = tid&31)
    {
        const int c  = tid >> 5;
        const int mm = tid & 31;
        float acc = 0.0f;
        #pragma unroll
        for (int ww = 0; ww < NWARP; ww++) acc += s_part[ww][c][mm];
        if (c == 0) s_dens[mm] = acc;
        __syncthreads();

        float tm = ti[(size_t)b * MMM + mbase + mm];
        float g  = uni ? ex2f(k2u * tm * tm) : 1.0f;
        float d0 = s_dens[mm] * g;                   // true density
        float inv = g / (d0 + 1e-8f);
        s_v[c][mm] = (c == 0) ? d0 : acc * inv;
        __syncthreads();
    }

    // stage 3: (8 -> 64) GEMM + bias; thread = (mm = tid>>3, og = tid&7), 8 outputs
    {
        const int mm = tid >> 3;
        const int og = tid & 7;
        float v[CC];
        #pragma unroll
        for (int c = 0; c < CC; c++) v[c] = s_v[c][mm];

        float4 r0 = *(const float4*)&s_bias[og * 8];
        float4 r1 = *(const float4*)&s_bias[og * 8 + 4];
        #pragma unroll
        for (int c = 0; c < CC; c++) {
            float4 w0 = *(const float4*)&s_Wt[c][og * 8];
            float4 w1 = *(const float4*)&s_Wt[c][og * 8 + 4];
            r0.x = fmaf(v[c], w0.x, r0.x);
            r0.y = fmaf(v[c], w0.y, r0.y);
            r0.z = fmaf(v[c], w0.z, r0.z);
            r0.w = fmaf(v[c], w0.w, r0.w);
            r1.x = fmaf(v[c], w1.x, r1.x);
            r1.y = fmaf(v[c], w1.y, r1.y);
            r1.z = fmaf(v[c], w1.z, r1.z);
            r1.w = fmaf(v[c], w1.w, r1.w);
        }
        float4* outp = (float4*)(out + ((size_t)(b * MMM + mbase + mm)) * COUT + og * 8);
        outp[0] = r0;
        outp[1] = r1;
    }
}

extern "C" void kernel_launch(void* const* d_in, const int* in_sizes, int n_in,
                              void* d_out, int out_size) {
    const float* ci    = (const float*)d_in[0];
    const float* co    = (const float*)d_in[1];
    const float* ti    = (const float*)d_in[2];
    const float* sigma = (const float*)d_in[3];
    const float* W     = (const float*)d_in[4];
    const float* bias  = (const float*)d_in[5];
    float* out = (float*)d_out;

    dim3 grid(BB * (MMM / MPB));   // 512 CTAs — one full wave at 4 CTAs/SM
    dim3 block(TPB);               // 256 threads (8 warps)
    convdeepset_kernel<<<grid, block>>>(ci, co, ti, sigma, W, bias, out);
}

// round 10
// speedup vs baseline: 1.4612x; 1.1604x over previous
#include <cuda_runtime.h>
#include <math.h>

#define BB    16
#define MMM   1024
#define NN    512
#define CC    8
#define COUT  64
#define NWARP 8               // warps per CTA
#define NSUB  (NWARP * 2)     // 16 virtual n-slices (half-warp each)
#define NPS   (NN / NSUB)     // 32 n per half-warp slice
#define MPB   64              // m per CTA (4 per lane, 16 lanes per half)
#define TPB   (32 * NWARP)    // 256 threads

__device__ __forceinline__ float ex2f(float x) {
    float y;
    asm("ex2.approx.ftz.f32 %0, %1;" : "=f"(y) : "f"(x));
    return y;
}
__device__ __forceinline__ unsigned long long pack2(float lo, float hi) {
    unsigned long long r;
    asm("mov.b64 %0, {%1, %2};" : "=l"(r) : "f"(lo), "f"(hi));
    return r;
}
__device__ __forceinline__ void unpack2(unsigned long long v, float& lo, float& hi) {
    asm("mov.b64 {%0, %1}, %2;" : "=f"(lo), "=f"(hi) : "l"(v));
}
__device__ __forceinline__ void ffma2(unsigned long long& d, unsigned long long a, unsigned long long b) {
    asm("fma.rn.f32x2 %0, %1, %2, %0;" : "+l"(d) : "l"(a), "l"(b));
}

__global__ __launch_bounds__(TPB)
void convdeepset_kernel(const float* __restrict__ ci,    // (B,N,1)
                        const float* __restrict__ co,    // (B,N,7)
                        const float* __restrict__ ti,    // (B,M,1)
                        const float* __restrict__ sigma, // (8,)
                        const float* __restrict__ W,     // (64,8)
                        const float* __restrict__ bias,  // (64,)
                        float* __restrict__ out)         // (B,M,64)
{
    __shared__ float4      s_ab2[NN / 2];            // (a_n,b_n,a_{n+1},b_{n+1}) per n-pair (4KB)
    __shared__ ulonglong2  s_cx[NN * 2];             // packed f32x2 channels (16KB)
    __shared__ float       s_part[NSUB][CC][MPB];    // 32KB: per virtual-slice partials
    __shared__ float       s_v[CC][MPB];
    __shared__ float       s_dens[MPB];
    __shared__ float       s_Wt[CC][COUT];
    __shared__ float       s_bias[COUT];

    const int tid  = threadIdx.x;
    const int w    = tid >> 5;
    const int lane = tid & 31;
    const int s    = lane >> 4;          // half-warp n-subslice
    const int ml   = lane & 15;          // local m (4 m's: ml + 16k)
    const int v    = w * 2 + s;          // virtual slice 0..15
    const int blk  = blockIdx.x;
    const int b    = blk >> 4;           // 16 m-tiles of 64 per batch
    const int mt   = blk & 15;
    const int mbase = mt * MPB;

    // stage W^T + bias (strided)
    for (int i = tid; i < CC * COUT; i += TPB) {
        int o = i / CC, c = i % CC;
        s_Wt[c][o] = W[i];
    }
    if (tid < COUT) s_bias[tid] = bias[tid];

    // uniform-sigma detection
    const float LOG2E = 1.4426950408889634f;
    float sg0 = sigma[0];
    bool uni = true;
    #pragma unroll
    for (int c = 1; c < CC; c++) uni &= (sigma[c] == sg0);
    const float k2u = -0.5f * LOG2E * expf(-2.0f * sg0);

    // stage context rows (2 per thread)
    const float* cib = ci + (size_t)b * NN;
    const float* cob = co + (size_t)b * NN * 7;
    float2* s_abf2 = (float2*)s_ab2;
    for (int i = tid; i < NN; i += TPB) {
        float x = cib[i];
        float2 ab;
        if (uni) { ab.x = k2u * x * x; ab.y = -2.0f * k2u * x; }
        else     { ab.x = x;           ab.y = 0.0f; }
        s_abf2[i] = ab;
        const float* r = cob + i * 7;
        s_cx[2 * i]     = make_ulonglong2(pack2(1.0f, r[0]), pack2(r[1], r[2]));
        s_cx[2 * i + 1] = make_ulonglong2(pack2(r[3], r[4]), pack2(r[5], r[6]));
    }
    __syncthreads();

    // 4 target positions per lane
    float t0 = ti[(size_t)b * MMM + mbase + ml];
    float t1 = ti[(size_t)b * MMM + mbase + ml + 16];
    float t2 = ti[(size_t)b * MMM + mbase + ml + 32];
    float t3 = ti[(size_t)b * MMM + mbase + ml + 48];

    const int n0 = v * NPS;   // this half-warp's n range [n0, n0+32)

    // accumulators: 4 m x 4 f32x2 channel-pairs
    unsigned long long acc[4][4];
    #pragma unroll
    for (int k = 0; k < 4; k++)
        #pragma unroll
        for (int j = 0; j < 4; j++) acc[k][j] = 0ull;

    float fown[4][CC];   // general-path f32 accumulators (unused in uni path)

    if (uni) {
        #pragma unroll 4
        for (int i = 0; i < NPS / 2; i++) {
            const int np = (n0 >> 1) + i;
            const int n  = n0 + 2 * i;
            float4 ab = s_ab2[np];
            ulonglong2 pa = s_cx[2 * n];
            ulonglong2 qa = s_cx[2 * n + 1];
            ulonglong2 pb = s_cx[2 * n + 2];
            ulonglong2 qb = s_cx[2 * n + 3];

            float wa0 = ex2f(fmaf(ab.y, t0, ab.x));
            float wb0 = ex2f(fmaf(ab.w, t0, ab.z));
            float wa1 = ex2f(fmaf(ab.y, t1, ab.x));
            float wb1 = ex2f(fmaf(ab.w, t1, ab.z));
            float wa2 = ex2f(fmaf(ab.y, t2, ab.x));
            float wb2 = ex2f(fmaf(ab.w, t2, ab.z));
            float wa3 = ex2f(fmaf(ab.y, t3, ab.x));
            float wb3 = ex2f(fmaf(ab.w, t3, ab.z));

            unsigned long long p;
            p = pack2(wa0, wa0);
            ffma2(acc[0][0], p, pa.x); ffma2(acc[0][1], p, pa.y);
            ffma2(acc[0][2], p, qa.x); ffma2(acc[0][3], p, qa.y);
            p = pack2(wb0, wb0);
            ffma2(acc[0][0], p, pb.x); ffma2(acc[0][1], p, pb.y);
            ffma2(acc[0][2], p, qb.x); ffma2(acc[0][3], p, qb.y);
            p = pack2(wa1, wa1);
            ffma2(acc[1][0], p, pa.x); ffma2(acc[1][1], p, pa.y);
            ffma2(acc[1][2], p, qa.x); ffma2(acc[1][3], p, qa.y);
            p = pack2(wb1, wb1);
            ffma2(acc[1][0], p, pb.x); ffma2(acc[1][1], p, pb.y);
            ffma2(acc[1][2], p, qb.x); ffma2(acc[1][3], p, qb.y);
            p = pack2(wa2, wa2);
            ffma2(acc[2][0], p, pa.x); ffma2(acc[2][1], p, pa.y);
            ffma2(acc[2][2], p, qa.x); ffma2(acc[2][3], p, qa.y);
            p = pack2(wb2, wb2);
            ffma2(acc[2][0], p, pb.x); ffma2(acc[2][1], p, pb.y);
            ffma2(acc[2][2], p, qb.x); ffma2(acc[2][3], p, qb.y);
            p = pack2(wa3, wa3);
            ffma2(acc[3][0], p, pa.x); ffma2(acc[3][1], p, pa.y);
            ffma2(acc[3][2], p, qa.x); ffma2(acc[3][3], p, qa.y);
            p = pack2(wb3, wb3);
            ffma2(acc[3][0], p, pb.x); ffma2(acc[3][1], p, pb.y);
            ffma2(acc[3][2], p, qb.x); ffma2(acc[3][3], p, qb.y);
        }
    } else {
        float k2[CC];
        #pragma unroll
        for (int c = 0; c < CC; c++) k2[c] = -0.5f * LOG2E * expf(-2.0f * sigma[c]);
        #pragma unroll
        for (int k = 0; k < 4; k++)
            #pragma unroll
            for (int c = 0; c < CC; c++) fown[k][c] = 0.0f;
        float tt[4] = {t0, t1, t2, t3};
        for (int i = 0; i < NPS; i++) {
            int n = n0 + i;
            float x = s_abf2[n].x;
            const float* cf = (const float*)&s_cx[2 * n];
            #pragma unroll
            for (int k = 0; k < 4; k++) {
                float diff = x - tt[k];
                float d = diff * diff;
                #pragma unroll
                for (int c = 0; c < CC; c++) fown[k][c] += ex2f(d * k2[c]) * cf[c];
            }
        }
    }

    // write per-slice partials
    if (uni) {
        #pragma unroll
        for (int k = 0; k < 4; k++) {
            float p0, p1, p2, p3, p4, p5, p6, p7;
            unpack2(acc[k][0], p0, p1);
            unpack2(acc[k][1], p2, p3);
            unpack2(acc[k][2], p4, p5);
            unpack2(acc[k][3], p6, p7);
            int mm = ml + 16 * k;
            s_part[v][0][mm] = p0; s_part[v][1][mm] = p1;
            s_part[v][2][mm] = p2; s_part[v][3][mm] = p3;
            s_part[v][4][mm] = p4; s_part[v][5][mm] = p5;
            s_part[v][6][mm] = p6; s_part[v][7][mm] = p7;
        }
    } else {
        #pragma unroll
        for (int k = 0; k < 4; k++) {
            int mm = ml + 16 * k;
            #pragma unroll
            for (int c = 0; c < CC; c++) s_part[v][c][mm] = fown[k][c];
        }
    }
    __syncthreads();

    // stage 2: reduce 16 slices; each thread handles 2 (c,mm) cells
    {
        #pragma unroll
        for (int rep = 0; rep < 2; rep++) {
            int idx = tid + rep * TPB;          // 0..511
            int c  = idx >> 6;
            int mm = idx & 63;
            float acc2 = 0.0f;
            #pragma unroll
            for (int vv = 0; vv < NSUB; vv++) acc2 += s_part[vv][c][mm];
            if (c == 0) s_dens[mm] = acc2;
            else        s_v[c][mm] = acc2;      // temp: raw sums
        }
        __syncthreads();
        #pragma unroll
        for (int rep = 0; rep < 2; rep++) {
            int idx = tid + rep * TPB;
            int c  = idx >> 6;
            int mm = idx & 63;
            float tm = ti[(size_t)b * MMM + mbase + mm];
            float g  = uni ? ex2f(k2u * tm * tm) : 1.0f;
            float d0 = s_dens[mm] * g;          // true density
            float inv = g / (d0 + 1e-8f);
            if (c == 0) s_v[0][mm] = d0;
            else        s_v[c][mm] = s_v[c][mm] * inv;
        }
        __syncthreads();
    }

    // stage 3: (8 -> 64) GEMM + bias; thread = (mm = tid>>2, og = tid&3), 16 outputs
    {
        const int mm = tid >> 2;
        const int og = tid & 3;
        float vv[CC];
        #pragma unroll
        for (int c = 0; c < CC; c++) vv[c] = s_v[c][mm];

        float4* outp = (float4*)(out + ((size_t)(b * MMM + mbase + mm)) * COUT + og * 16);
        #pragma unroll
        for (int j = 0; j < 4; j++) {
            int o4 = og * 4 + j;
            float4 r = *(const float4*)&s_bias[o4 * 4];
            #pragma unroll
            for (int c = 0; c < CC; c++) {
                float4 w4 = *(const float4*)&s_Wt[c][o4 * 4];
                r.x = fmaf(vv[c], w4.x, r.x);
                r.y = fmaf(vv[c], w4.y, r.y);
                r.z = fmaf(vv[c], w4.z, r.z);
                r.w = fmaf(vv[c], w4.w, r.w);
            }
            outp[j] = r;
        }
    }
}

extern "C" void kernel_launch(void* const* d_in, const int* in_sizes, int n_in,
                              void* d_out, int out_size) {
    const float* ci    = (const float*)d_in[0];
    const float* co    = (const float*)d_in[1];
    const float* ti    = (const float*)d_in[2];
    const float* sigma = (const float*)d_in[3];
    const float* W     = (const float*)d_in[4];
    const float* bias  = (const float*)d_in[5];
    float* out = (float*)d_out;

    dim3 grid(BB * (MMM / MPB));   // 256 CTAs
    dim3 block(TPB);               // 256 threads (8 warps, 16 half-warp n-slices)
    convdeepset_kernel<<<grid, block>>>(ci, co, ti, sigma, W, bias, out);
}